// round 15
// baseline (speedup 1.0000x reference)
#include <cuda_runtime.h>
#include <cuda_bf16.h>
#include <cstdint>

// LSTM: B=4096, T=2048, I=3, H=32.  out = h_final [B, H] fp32.
// Inputs: x [B,T,I], W_ih [4H,I], W_hh [4H,H], b_ih [4H], b_hh [4H]
//
// Balanced single wave (R11): 296 blocks x 4 warps = 1184 warps = exactly
// 2 blocks/SM. Blocks 0..135: 4 rows/warp; blocks 136..295: 3 rows/warp.
// Max SMSP load 7 rows. W_hh register-resident packed for fma.rn.f32x2
// (shared across rows); h via per-warp smem parity buffer read as LDS.128
// pre-packed pairs; x via padded smem; pipelined gmem staging.
// R12: hardware tanh.approx activations (measured rel_err 4.1e-6).
// R13: i/f/o gate weights+biases PRE-HALVED at load (exact: exponent-only
//      scale) so sigmoid(x) = fma(0.5, tanh(y), 0.5) on the halved preact
//      needs no 0.5*x multiply (-3 fma/row-step, -4 cyc per sigmoid chain);
//      inner unroll 4 for a wider scheduling window.

#define BB 4096
#define TT 2048
#define II 3
#define HH 32
#define RPWMAX 4
#define WPB 4            // warps per block
#define NBLK4 136        // blocks whose warps take 4 rows
#define NWARP4 (NBLK4 * WPB)       // 544
#define ROWS4 (NWARP4 * 4)         // 2176
#define GRID (148 * 2)             // 296 blocks = 1184 warps, 2 blocks/SM

typedef unsigned long long u64;

__device__ __forceinline__ u64 pack2(float x, float y) {
    u64 r; asm("mov.b64 %0, {%1, %2};" : "=l"(r) : "f"(x), "f"(y)); return r;
}
__device__ __forceinline__ void unpack2(u64 v, float& a, float& b) {
    asm("mov.b64 {%0, %1}, %2;" : "=f"(a), "=f"(b) : "l"(v));
}
// Blackwell packed dual-fp32 fma: d.lo = a.lo*b.lo + c.lo ; d.hi = a.hi*b.hi + c.hi
__device__ __forceinline__ u64 ffma2(u64 a, u64 b, u64 c) {
    u64 d; asm("fma.rn.f32x2 %0, %1, %2, %3;" : "=l"(d) : "l"(a), "l"(b), "l"(c));
    return d;
}

// hardware tanh (sm_75+): single MUFU op, max abs err ~4.9e-4
__device__ __forceinline__ float tanha(float x) {
    float r; asm("tanh.approx.f32 %0, %1;" : "=f"(r) : "f"(x)); return r;
}
// sigmoid from a PRE-HALVED preactivation y = x/2:
// sigm(x) = 0.5 + 0.5*tanh(x/2) = fma(0.5, tanh(y), 0.5)
__device__ __forceinline__ float sigm_h(float y) {
    return fmaf(0.5f, tanha(y), 0.5f);
}

// per-row LSTM epilogue: gates -> (h, c) update.
// aI/aF/aO accumulators carry HALVED preactivations (weights pre-scaled).
__device__ __forceinline__ void epi(u64 aI, u64 aF, u64 aG, u64 aO,
                                    float& h, float& c) {
    float l0, m0, l1, m1, l2, m2, l3, m3;
    unpack2(aI, l0, m0); unpack2(aF, l1, m1);
    unpack2(aG, l2, m2); unpack2(aO, l3, m3);
    // g first: it heads the longest serial chain (g -> c -> tanh(c) -> h)
    float gg = l2 + m2, gi = l0 + m0, gf = l1 + m1, go = l3 + m3;
    float gv = tanha(gg);
    float ig = sigm_h(gi), fg = sigm_h(gf), og = sigm_h(go);
    c = fmaf(fg, c, ig * gv);
    h = og * tanha(c);
}

// The full per-warp LSTM over R batch rows. R is compile-time (3 or 4).
template<int R>
__device__ __forceinline__ void lstm_body(
    int lane, int wib, int b0,
    const float* __restrict__ x,
    const float* __restrict__ W_ih,
    const float* __restrict__ W_hh,
    const float* __restrict__ b_ih,
    const float* __restrict__ b_hh,
    float* __restrict__ out,
    float (&hbuf)[WPB][2][RPWMAX][HH],
    float (&xbuf)[WPB][RPWMAX][32][4])
{
    const int gi_ = lane, gf_ = lane + 32, gg_ = lane + 64, go_ = lane + 96;

    // ---- W_hh rows into registers, packed along k in pairs (shared by rows).
    // i/f/o rows pre-scaled by 0.5 (exact); g row full-scale.
    u64 WI[16], WF[16], WG[16], WO[16];
    {
        const float2* wi = reinterpret_cast<const float2*>(W_hh + gi_ * HH);
        const float2* wf = reinterpret_cast<const float2*>(W_hh + gf_ * HH);
        const float2* wg = reinterpret_cast<const float2*>(W_hh + gg_ * HH);
        const float2* wo = reinterpret_cast<const float2*>(W_hh + go_ * HH);
#pragma unroll
        for (int k = 0; k < 16; ++k) {
            float2 a;
            a = wi[k]; WI[k] = pack2(0.5f * a.x, 0.5f * a.y);
            a = wf[k]; WF[k] = pack2(0.5f * a.x, 0.5f * a.y);
            a = wg[k]; WG[k] = pack2(a.x, a.y);
            a = wo[k]; WO[k] = pack2(0.5f * a.x, 0.5f * a.y);
        }
    }

    // ---- W_ih rows (I=3): packed (w0,w1) and (w2,0); i/f/o pre-halved ----
    const u64 XI0 = pack2(0.5f * W_ih[gi_*II + 0], 0.5f * W_ih[gi_*II + 1]);
    const u64 XI2 = pack2(0.5f * W_ih[gi_*II + 2], 0.0f);
    const u64 XF0 = pack2(0.5f * W_ih[gf_*II + 0], 0.5f * W_ih[gf_*II + 1]);
    const u64 XF2 = pack2(0.5f * W_ih[gf_*II + 2], 0.0f);
    const u64 XG0 = pack2(W_ih[gg_*II + 0], W_ih[gg_*II + 1]);
    const u64 XG2 = pack2(W_ih[gg_*II + 2], 0.0f);
    const u64 XO0 = pack2(0.5f * W_ih[go_*II + 0], 0.5f * W_ih[go_*II + 1]);
    const u64 XO2 = pack2(0.5f * W_ih[go_*II + 2], 0.0f);

    // ---- biases (b_ih + b_hh), i/f/o pre-halved, folded into acc init ----
    const u64 BI = pack2(0.5f * (b_ih[gi_] + b_hh[gi_]), 0.0f);
    const u64 BF = pack2(0.5f * (b_ih[gf_] + b_hh[gf_]), 0.0f);
    const u64 BG = pack2(b_ih[gg_] + b_hh[gg_], 0.0f);
    const u64 BO = pack2(0.5f * (b_ih[go_] + b_hh[go_]), 0.0f);

    const float* xp[R];
#pragma unroll
    for (int r = 0; r < R; ++r)
        xp[r] = x + (size_t)(b0 + r) * (TT * II);

    float h[R], c[R];
#pragma unroll
    for (int r = 0; r < R; ++r) { h[r] = 0.0f; c[r] = 0.0f; }

    // init h parity-0 buffer with h_{-1} = 0; zero xbuf pad words once
#pragma unroll
    for (int r = 0; r < R; ++r) {
        hbuf[wib][0][r][lane] = 0.0f;
        xbuf[wib][r][lane][3] = 0.0f;
    }

    // ---- prefetch chunk 0 x into registers (coalesced) ----
    float pA[R], pB[R], pC[R];
#pragma unroll
    for (int r = 0; r < R; ++r) {
        pA[r] = xp[r][lane];
        pB[r] = xp[r][32 + lane];
        pC[r] = xp[r][64 + lane];
    }

    // staging remap: flat index j in [0,96) -> (step j/3, comp j%3)
    const int tA = lane / 3,        cA = lane - 3 * tA;
    const int tB = (32 + lane) / 3, cB = (32 + lane) - 3 * tB;
    const int tC = (64 + lane) / 3, cC = (64 + lane) - 3 * tC;

    int p = 0;
    __syncwarp();

    for (int t0 = 0; t0 < TT; t0 += 32) {
        // stage current chunk's x into smem (remapped to 4-float stride)
#pragma unroll
        for (int r = 0; r < R; ++r) {
            float* xr = &xbuf[wib][r][0][0];
            xr[4*tA + cA] = pA[r];
            xr[4*tB + cB] = pB[r];
            xr[4*tC + cC] = pC[r];
        }

        // prefetch next chunk (hides DRAM latency under 32 inner steps)
        if (t0 + 32 < TT) {
#pragma unroll
            for (int r = 0; r < R; ++r) {
                const float* xn = xp[r] + (t0 + 32) * II;
                pA[r] = xn[lane];
                pB[r] = xn[32 + lane];
                pC[r] = xn[64 + lane];
            }
        }
        __syncwarp();

#pragma unroll 4
        for (int s = 0; s < 32; ++s) {
            u64 aI[R], aF[R], aG[R], aO[R];

            // x: one LDS.128 per row; .x = packed (x0,x1), .y = (x2, 0)
#pragma unroll
            for (int r = 0; r < R; ++r) {
                ulonglong2 xv = *reinterpret_cast<const ulonglong2*>(&xbuf[wib][r][s][0]);
                aI[r] = ffma2(XI0, xv.x, BI); aI[r] = ffma2(XI2, xv.y, aI[r]);
                aF[r] = ffma2(XF0, xv.x, BF); aF[r] = ffma2(XF2, xv.y, aF[r]);
                aG[r] = ffma2(XG0, xv.x, BG); aG[r] = ffma2(XG2, xv.y, aG[r]);
                aO[r] = ffma2(XO0, xv.x, BO); aO[r] = ffma2(XO2, xv.y, aO[r]);
            }

            // recurrent matvec: 8 LDS.128 per row, bits are pre-packed f32x2 pairs
#pragma unroll
            for (int k = 0; k < 8; ++k) {
                const u64 wA_i = WI[2*k], wB_i = WI[2*k+1];
                const u64 wA_f = WF[2*k], wB_f = WF[2*k+1];
                const u64 wA_g = WG[2*k], wB_g = WG[2*k+1];
                const u64 wA_o = WO[2*k], wB_o = WO[2*k+1];
#pragma unroll
                for (int r = 0; r < R; ++r) {
                    ulonglong2 q = *reinterpret_cast<const ulonglong2*>(
                        &hbuf[wib][p][r][0] + 4 * k);
                    aI[r] = ffma2(wA_i, q.x, aI[r]); aI[r] = ffma2(wB_i, q.y, aI[r]);
                    aF[r] = ffma2(wA_f, q.x, aF[r]); aF[r] = ffma2(wB_f, q.y, aF[r]);
                    aG[r] = ffma2(wA_g, q.x, aG[r]); aG[r] = ffma2(wB_g, q.y, aG[r]);
                    aO[r] = ffma2(wA_o, q.x, aO[r]); aO[r] = ffma2(wB_o, q.y, aO[r]);
                }
            }

#pragma unroll
            for (int r = 0; r < R; ++r)
                epi(aI[r], aF[r], aG[r], aO[r], h[r], c[r]);

            // publish h for next step into the other parity buffer
#pragma unroll
            for (int r = 0; r < R; ++r)
                hbuf[wib][p ^ 1][r][lane] = h[r];
            __syncwarp();
            p ^= 1;
        }
    }

#pragma unroll
    for (int r = 0; r < R; ++r)
        out[(b0 + r) * HH + lane] = h[r];
}

__global__ void __launch_bounds__(32 * WPB)
lstm_balanced(const float* __restrict__ x,
              const float* __restrict__ W_ih,
              const float* __restrict__ W_hh,
              const float* __restrict__ b_ih,
              const float* __restrict__ b_hh,
              float* __restrict__ out)
{
    // [warp][parity][row][hidden] - 128B row stride, 16B aligned for LDS.128
    __shared__ __align__(16) float hbuf[WPB][2][RPWMAX][HH];
    // [warp][row][step][4]  (x0,x1,x2,0) -> one LDS.128 per row-step
    __shared__ __align__(16) float xbuf[WPB][RPWMAX][32][4];

    const int lane = threadIdx.x & 31;
    const int wib  = threadIdx.x >> 5;
    const int gw   = blockIdx.x * WPB + wib;

    // Branch is uniform per block (block 0..135 all-4row, 136..295 all-3row).
    if (gw < NWARP4) {
        const int b0 = gw * 4;                      // rows [0, 2176)
        lstm_body<4>(lane, wib, b0, x, W_ih, W_hh, b_ih, b_hh, out, hbuf, xbuf);
    } else {
        const int b0 = ROWS4 + (gw - NWARP4) * 3;   // rows [2176, 4096)
        lstm_body<3>(lane, wib, b0, x, W_ih, W_hh, b_ih, b_hh, out, hbuf, xbuf);
    }
}

extern "C" void kernel_launch(void* const* d_in, const int* in_sizes, int n_in,
                              void* d_out, int out_size) {
    const float* x    = (const float*)d_in[0];
    const float* W_ih = (const float*)d_in[1];
    const float* W_hh = (const float*)d_in[2];
    const float* b_ih = (const float*)d_in[3];
    const float* b_hh = (const float*)d_in[4];
    float* out = (float*)d_out;

    // 296 blocks x 4 warps = 1184 warps = exactly 2 blocks per SM, one wave.
    dim3 block(32 * WPB);
    dim3 grid(GRID);
    lstm_balanced<<<grid, block>>>(x, W_ih, W_hh, b_ih, b_hh, out);
}